// round 8
// baseline (speedup 1.0000x reference)
#include <cuda_runtime.h>
#include <cstdint>

#define EPS 1e-5f

__device__ __forceinline__ float tanh_fast(float x) {
    float y; asm("tanh.approx.f32 %0,%1;" : "=f"(y) : "f"(x)); return y;
}
__device__ __forceinline__ unsigned cvt_tf32(float x) {
    unsigned u; asm("cvt.rna.tf32.f32 %0,%1;" : "=r"(u) : "f"(x)); return u;
}
__device__ __forceinline__ float tf32f(float x) { return __uint_as_float(cvt_tf32(x)); }

__device__ __forceinline__ void mma8(float* d,
                                     unsigned a0, unsigned a1, unsigned a2, unsigned a3,
                                     unsigned b0, unsigned b1) {
    asm volatile(
        "mma.sync.aligned.m16n8k8.row.col.f32.tf32.tf32.f32 "
        "{%0,%1,%2,%3},{%4,%5,%6,%7},{%8,%9},{%0,%1,%2,%3};"
        : "+f"(d[0]), "+f"(d[1]), "+f"(d[2]), "+f"(d[3])
        : "r"(a0), "r"(a1), "r"(a2), "r"(a3), "r"(b0), "r"(b1));
}

// hb row stride (floats): 68 -> conflict-free A-fragment loads
#define HSTR 68

__device__ __forceinline__ void init_bias(float d[2][8][4], const float* __restrict__ sb, int tg) {
#pragma unroll
    for (int nt = 0; nt < 8; nt++) {
        float2 bb = *(const float2*)&sb[8 * nt + 2 * tg];
        d[0][nt][0] = bb.x; d[0][nt][1] = bb.y; d[0][nt][2] = bb.x; d[0][nt][3] = bb.y;
        d[1][nt][0] = bb.x; d[1][nt][1] = bb.y; d[1][nt][2] = bb.x; d[1][nt][3] = bb.y;
    }
}

template <int NKK>
__device__ __forceinline__ void mma_layer(float d[2][8][4], const float* __restrict__ bf,
                                          const float* __restrict__ hb, int g, int tg, int lane) {
#pragma unroll
    for (int kk = 0; kk < NKK; kk++) {
        unsigned A[2][4];
#pragma unroll
        for (int mt = 0; mt < 2; mt++) {
            A[mt][0] = __float_as_uint(hb[(16 * mt + g) * HSTR + 8 * kk + tg]);
            A[mt][1] = __float_as_uint(hb[(16 * mt + g + 8) * HSTR + 8 * kk + tg]);
            A[mt][2] = __float_as_uint(hb[(16 * mt + g) * HSTR + 8 * kk + tg + 4]);
            A[mt][3] = __float_as_uint(hb[(16 * mt + g + 8) * HSTR + 8 * kk + tg + 4]);
        }
#pragma unroll
        for (int nt = 0; nt < 8; nt++) {
            float2 w = *(const float2*)&bf[((kk * 8 + nt) * 32 + lane) * 2];
            unsigned b0 = __float_as_uint(w.x), b1 = __float_as_uint(w.y);
            mma8(d[0][nt], A[0][0], A[0][1], A[0][2], A[0][3], b0, b1);
            mma8(d[1][nt], A[1][0], A[1][1], A[1][2], A[1][3], b0, b1);
        }
    }
}

// One-pass LN (sum + sumsq) + tanh, optional tf32 store back to hb.
template <bool STORE>
__device__ __forceinline__ void ln_tanh_frag(float d[2][8][4],
                                             const float* __restrict__ sg,
                                             const float* __restrict__ sbe,
                                             float* __restrict__ hb, int g, int tg) {
#pragma unroll
    for (int mt = 0; mt < 2; mt++) {
        float s1 = 0.f, q1 = 0.f, s2 = 0.f, q2 = 0.f;
#pragma unroll
        for (int nt = 0; nt < 8; nt++) {
            float a = d[mt][nt][0], b = d[mt][nt][1];
            float c = d[mt][nt][2], e = d[mt][nt][3];
            s1 += a + b; q1 = fmaf(a, a, q1); q1 = fmaf(b, b, q1);
            s2 += c + e; q2 = fmaf(c, c, q2); q2 = fmaf(e, e, q2);
        }
        s1 += __shfl_xor_sync(0xffffffffu, s1, 1); q1 += __shfl_xor_sync(0xffffffffu, q1, 1);
        s2 += __shfl_xor_sync(0xffffffffu, s2, 1); q2 += __shfl_xor_sync(0xffffffffu, q2, 1);
        s1 += __shfl_xor_sync(0xffffffffu, s1, 2); q1 += __shfl_xor_sync(0xffffffffu, q1, 2);
        s2 += __shfl_xor_sync(0xffffffffu, s2, 2); q2 += __shfl_xor_sync(0xffffffffu, q2, 2);
        float m1 = s1 * (1.f / 64.f), m2 = s2 * (1.f / 64.f);
        float v1 = fmaf(-m1, m1, q1 * (1.f / 64.f));
        float v2 = fmaf(-m2, m2, q2 * (1.f / 64.f));
        float i1 = rsqrtf(v1 + EPS);
        float i2 = rsqrtf(v2 + EPS);
#pragma unroll
        for (int nt = 0; nt < 8; nt++) {
            float2 gg = *(const float2*)&sg[8 * nt + 2 * tg];
            float2 bb = *(const float2*)&sbe[8 * nt + 2 * tg];
            d[mt][nt][0] = tanh_fast(fmaf((d[mt][nt][0] - m1) * i1, gg.x, bb.x));
            d[mt][nt][1] = tanh_fast(fmaf((d[mt][nt][1] - m1) * i1, gg.y, bb.y));
            d[mt][nt][2] = tanh_fast(fmaf((d[mt][nt][2] - m2) * i2, gg.x, bb.x));
            d[mt][nt][3] = tanh_fast(fmaf((d[mt][nt][3] - m2) * i2, gg.y, bb.y));
            if (STORE) {
                float2 lo = make_float2(tf32f(d[mt][nt][0]), tf32f(d[mt][nt][1]));
                float2 hi = make_float2(tf32f(d[mt][nt][2]), tf32f(d[mt][nt][3]));
                *(float2*)&hb[(16 * mt + g) * HSTR + 8 * nt + 2 * tg] = lo;
                *(float2*)&hb[(16 * mt + g + 8) * HSTR + 8 * nt + 2 * tg] = hi;
            }
        }
    }
}

// smem layout (floats):
// BF0 [1024] @ 0 | BF1 [4096] @ 1024 | BF2 [4096] @ 5120
// sb0/sb1/sb2/sg0/sbe0/sg1/sbe1/sg2/sbe2/sw3 (64 each) @ 9216..9855
// hb: 8 warps x 32 rows x HSTR @ 9856
#define SMEM_FLOATS (9856 + 8 * 32 * HSTR)

__global__ __launch_bounds__(256, 2) void edge_mlp_tc(
    const float* __restrict__ x, const int* __restrict__ ei,
    const float* __restrict__ W0, const float* __restrict__ b0,
    const float* __restrict__ g0, const float* __restrict__ be0,
    const float* __restrict__ W1, const float* __restrict__ b1,
    const float* __restrict__ g1, const float* __restrict__ be1,
    const float* __restrict__ W2, const float* __restrict__ b2,
    const float* __restrict__ g2, const float* __restrict__ be2,
    const float* __restrict__ W3, const float* __restrict__ b3,
    float* __restrict__ out, int n_edges)
{
    extern __shared__ float sm[];
    float* BF0 = sm;
    float* BF1 = sm + 1024;
    float* BF2 = sm + 5120;
    float* sb0 = sm + 9216; float* sb1 = sm + 9280; float* sb2 = sm + 9344;
    float* sg0 = sm + 9408; float* sbe0 = sm + 9472;
    float* sg1 = sm + 9536; float* sbe1 = sm + 9600;
    float* sg2 = sm + 9664; float* sbe2 = sm + 9728;
    float* sw3 = sm + 9792;

    const int tid = threadIdx.x;

    // Stage B fragments: b0 = W[8kk+t][8nt+g], b1 = W[8kk+t+4][8nt+g]
    for (int i = tid; i < 512; i += 256) {
        int kk = i >> 8, rem = i & 255, nt = rem >> 5, ln = rem & 31;
        int gg = ln >> 2, tt = ln & 3;
        int r = 8 * kk + tt, c = 8 * nt + gg;
        BF0[2 * i]     = tf32f(W0[r * 64 + c]);
        BF0[2 * i + 1] = tf32f(W0[(r + 4) * 64 + c]);
    }
    for (int i = tid; i < 2048; i += 256) {
        int kk = i >> 8, rem = i & 255, nt = rem >> 5, ln = rem & 31;
        int gg = ln >> 2, tt = ln & 3;
        int r = 8 * kk + tt, c = 8 * nt + gg;
        BF1[2 * i]     = tf32f(W1[r * 64 + c]);
        BF1[2 * i + 1] = tf32f(W1[(r + 4) * 64 + c]);
        BF2[2 * i]     = tf32f(W2[r * 64 + c]);
        BF2[2 * i + 1] = tf32f(W2[(r + 4) * 64 + c]);
    }
    if (tid < 64) {
        sb0[tid] = b0[tid]; sb1[tid] = b1[tid]; sb2[tid] = b2[tid];
        sg0[tid] = g0[tid]; sbe0[tid] = be0[tid];
        sg1[tid] = g1[tid]; sbe1[tid] = be1[tid];
        sg2[tid] = g2[tid]; sbe2[tid] = be2[tid];
        sw3[tid] = W3[tid];
    }
    __syncthreads();
    const float b3v = b3[0];

    const int lane = tid & 31, wid = tid >> 5;
    const int g = lane >> 2, tg = lane & 3;
    float* hb = sm + 9856 + wid * (32 * HSTR);
    const float4* x4 = (const float4*)x;

    const int tile_stride = gridDim.x * 8 * 32;
    int base = (blockIdx.x * 8 + wid) * 32;
    if (base >= n_edges) return;

    // Prologue gather (tile 0)
    int e = base + lane; if (e >= n_edges) e = n_edges - 1;
    int si = ei[e], di = ei[n_edges + e];
    float4 A0 = x4[2 * si], A1 = x4[2 * si + 1];
    float4 C0 = x4[2 * di], C1 = x4[2 * di + 1];

    for (; base < n_edges; base += tile_stride) {
        // Commit current gather to hb (tf32-rounded)
        float* hr = &hb[lane * HSTR];
        *(float4*)&hr[0]  = make_float4(tf32f(A0.x), tf32f(A0.y), tf32f(A0.z), tf32f(A0.w));
        *(float4*)&hr[4]  = make_float4(tf32f(A1.x), tf32f(A1.y), tf32f(A1.z), tf32f(A1.w));
        *(float4*)&hr[8]  = make_float4(tf32f(C0.x), tf32f(C0.y), tf32f(C0.z), tf32f(C0.w));
        *(float4*)&hr[12] = make_float4(tf32f(C1.x), tf32f(C1.y), tf32f(C1.z), tf32f(C1.w));
        __syncwarp();

        // Prefetch next tile indices now (consumed after layer 0)
        int nbase = base + tile_stride;
        int ne = e;
        if (nbase < n_edges) {
            ne = nbase + lane; if (ne >= n_edges) ne = n_edges - 1;
        }
        int nsi = ei[ne], ndi = ei[n_edges + ne];

        float d[2][8][4];

        // layer 0: K=16
        init_bias(d, sb0, tg);
        mma_layer<2>(d, BF0, hb, g, tg, lane);
        __syncwarp();
        ln_tanh_frag<true>(d, sg0, sbe0, hb, g, tg);
        __syncwarp();

        // Prefetch next tile x rows (indices have landed by now)
        float4 nA0 = x4[2 * nsi], nA1 = x4[2 * nsi + 1];
        float4 nC0 = x4[2 * ndi], nC1 = x4[2 * ndi + 1];

        // layer 1: K=64
        init_bias(d, sb1, tg);
        mma_layer<8>(d, BF1, hb, g, tg, lane);
        __syncwarp();
        ln_tanh_frag<true>(d, sg1, sbe1, hb, g, tg);
        __syncwarp();

        // layer 2: K=64 (output stays in registers)
        init_bias(d, sb2, tg);
        mma_layer<8>(d, BF2, hb, g, tg, lane);
        __syncwarp();   // all lanes done reading hb -> safe to overwrite next iter
        ln_tanh_frag<false>(d, sg2, sbe2, hb, g, tg);

        // layer 3: 64 -> 1, butterfly reduce over the 4-lane group
#pragma unroll
        for (int mt = 0; mt < 2; mt++) {
            float p1 = 0.f, p2 = 0.f;
#pragma unroll
            for (int nt = 0; nt < 8; nt++) {
                float2 w = *(const float2*)&sw3[8 * nt + 2 * tg];
                p1 = fmaf(d[mt][nt][0], w.x, p1); p1 = fmaf(d[mt][nt][1], w.y, p1);
                p2 = fmaf(d[mt][nt][2], w.x, p2); p2 = fmaf(d[mt][nt][3], w.y, p2);
            }
            p1 += __shfl_xor_sync(0xffffffffu, p1, 1); p1 += __shfl_xor_sync(0xffffffffu, p1, 2);
            p2 += __shfl_xor_sync(0xffffffffu, p2, 1); p2 += __shfl_xor_sync(0xffffffffu, p2, 2);
            if (tg == 0) {
                int e1 = base + 16 * mt + g, e2 = e1 + 8;
                if (e1 < n_edges) out[e1] = p1 + b3v;
                if (e2 < n_edges) out[e2] = p2 + b3v;
            }
        }

        // rotate prefetched gather
        A0 = nA0; A1 = nA1; C0 = nC0; C1 = nC1;
        e = ne;
    }
}

extern "C" void kernel_launch(void* const* d_in, const int* in_sizes, int n_in,
                              void* d_out, int out_size) {
    const float* x   = (const float*)d_in[0];
    const int*   ei  = (const int*)d_in[1];
    const float* W0 = (const float*)d_in[2];
    const float* b0 = (const float*)d_in[3];
    const float* g0 = (const float*)d_in[4];
    const float* be0 = (const float*)d_in[5];
    const float* W1 = (const float*)d_in[6];
    const float* b1 = (const float*)d_in[7];
    const float* g1 = (const float*)d_in[8];
    const float* be1 = (const float*)d_in[9];
    const float* W2 = (const float*)d_in[10];
    const float* b2 = (const float*)d_in[11];
    const float* g2 = (const float*)d_in[12];
    const float* be2 = (const float*)d_in[13];
    const float* W3 = (const float*)d_in[14];
    const float* b3 = (const float*)d_in[15];
    float* out = (float*)d_out;

    const int n_edges = in_sizes[1] / 2;
    const size_t smem_bytes = SMEM_FLOATS * sizeof(float);  // ~106.5 KB

    static bool attr_set = false;
    if (!attr_set) {
        cudaFuncSetAttribute(edge_mlp_tc, cudaFuncAttributeMaxDynamicSharedMemorySize,
                             (int)smem_bytes);
        attr_set = true;
    }

    const int threads = 256;
    const int blocks = 296;  // 2 resident blocks/SM, grid-stride
    edge_mlp_tc<<<blocks, threads, smem_bytes>>>(x, ei,
                                                 W0, b0, g0, be0,
                                                 W1, b1, g1, be1,
                                                 W2, b2, g2, be2,
                                                 W3, b3, out, n_edges);
}

// round 9
// speedup vs baseline: 1.5502x; 1.5502x over previous
#include <cuda_runtime.h>
#include <cuda_fp16.h>
#include <cstdint>

#define EPS 1e-5f

__device__ __forceinline__ float tanh_fast(float x) {
    float y; asm("tanh.approx.f32 %0,%1;" : "=f"(y) : "f"(x)); return y;
}
__device__ __forceinline__ unsigned packh2(float a, float b) {
    __half2 h = __floats2half2_rn(a, b);
    return *reinterpret_cast<unsigned*>(&h);
}

__device__ __forceinline__ void mma16(float* d,
                                      unsigned a0, unsigned a1, unsigned a2, unsigned a3,
                                      unsigned b0, unsigned b1) {
    asm volatile(
        "mma.sync.aligned.m16n8k16.row.col.f32.f16.f16.f32 "
        "{%0,%1,%2,%3},{%4,%5,%6,%7},{%8,%9},{%0,%1,%2,%3};"
        : "+f"(d[0]), "+f"(d[1]), "+f"(d[2]), "+f"(d[3])
        : "r"(a0), "r"(a1), "r"(a2), "r"(a3), "r"(b0), "r"(b1));
}

// hb row stride: 72 halfs = 36 u32 words -> (4g+tg)%32 unique => conflict-free
#define HSTRW 36

__device__ __forceinline__ void init_bias(float d[2][8][4], const float* __restrict__ sb, int tg) {
#pragma unroll
    for (int nt = 0; nt < 8; nt++) {
        float2 bb = *(const float2*)&sb[8 * nt + 2 * tg];
        d[0][nt][0] = bb.x; d[0][nt][1] = bb.y; d[0][nt][2] = bb.x; d[0][nt][3] = bb.y;
        d[1][nt][0] = bb.x; d[1][nt][1] = bb.y; d[1][nt][2] = bb.x; d[1][nt][3] = bb.y;
    }
}

// A frag (row g / g+8 within mt block, cols 16kk + {2tg,2tg+1, 2tg+8,2tg+9}):
template <int NKK>
__device__ __forceinline__ void mma_layer(float d[2][8][4], const uint2* __restrict__ bf,
                                          const unsigned* __restrict__ hbu,
                                          int g, int tg, int lane) {
#pragma unroll
    for (int kk = 0; kk < NKK; kk++) {
        unsigned A[2][4];
#pragma unroll
        for (int mt = 0; mt < 2; mt++) {
            const int r0 = (16 * mt + g) * HSTRW, r1 = (16 * mt + g + 8) * HSTRW;
            A[mt][0] = hbu[r0 + 8 * kk + tg];
            A[mt][1] = hbu[r1 + 8 * kk + tg];
            A[mt][2] = hbu[r0 + 8 * kk + tg + 4];
            A[mt][3] = hbu[r1 + 8 * kk + tg + 4];
        }
#pragma unroll
        for (int nt = 0; nt < 8; nt++) {
            uint2 b = bf[(kk * 8 + nt) * 32 + lane];
            mma16(d[0][nt], A[0][0], A[0][1], A[0][2], A[0][3], b.x, b.y);
            mma16(d[1][nt], A[1][0], A[1][1], A[1][2], A[1][3], b.x, b.y);
        }
    }
}

// One-pass LN (sum + sumsq) + tanh, optional half2 store back to hb.
template <bool STORE>
__device__ __forceinline__ void ln_tanh_frag(float d[2][8][4],
                                             const float* __restrict__ sg,
                                             const float* __restrict__ sbe,
                                             unsigned* __restrict__ hbu, int g, int tg) {
#pragma unroll
    for (int mt = 0; mt < 2; mt++) {
        float s1 = 0.f, q1 = 0.f, s2 = 0.f, q2 = 0.f;
#pragma unroll
        for (int nt = 0; nt < 8; nt++) {
            float a = d[mt][nt][0], b = d[mt][nt][1];
            float c = d[mt][nt][2], e = d[mt][nt][3];
            s1 += a + b; q1 = fmaf(a, a, q1); q1 = fmaf(b, b, q1);
            s2 += c + e; q2 = fmaf(c, c, q2); q2 = fmaf(e, e, q2);
        }
        s1 += __shfl_xor_sync(0xffffffffu, s1, 1); q1 += __shfl_xor_sync(0xffffffffu, q1, 1);
        s2 += __shfl_xor_sync(0xffffffffu, s2, 1); q2 += __shfl_xor_sync(0xffffffffu, q2, 1);
        s1 += __shfl_xor_sync(0xffffffffu, s1, 2); q1 += __shfl_xor_sync(0xffffffffu, q1, 2);
        s2 += __shfl_xor_sync(0xffffffffu, s2, 2); q2 += __shfl_xor_sync(0xffffffffu, q2, 2);
        float m1 = s1 * (1.f / 64.f), m2 = s2 * (1.f / 64.f);
        float i1 = rsqrtf(fmaf(-m1, m1, q1 * (1.f / 64.f)) + EPS);
        float i2 = rsqrtf(fmaf(-m2, m2, q2 * (1.f / 64.f)) + EPS);
#pragma unroll
        for (int nt = 0; nt < 8; nt++) {
            float2 gg = *(const float2*)&sg[8 * nt + 2 * tg];
            float2 bb = *(const float2*)&sbe[8 * nt + 2 * tg];
            d[mt][nt][0] = tanh_fast(fmaf((d[mt][nt][0] - m1) * i1, gg.x, bb.x));
            d[mt][nt][1] = tanh_fast(fmaf((d[mt][nt][1] - m1) * i1, gg.y, bb.y));
            d[mt][nt][2] = tanh_fast(fmaf((d[mt][nt][2] - m2) * i2, gg.x, bb.x));
            d[mt][nt][3] = tanh_fast(fmaf((d[mt][nt][3] - m2) * i2, gg.y, bb.y));
            if (STORE) {
                hbu[(16 * mt + g) * HSTRW + 4 * nt + tg]     = packh2(d[mt][nt][0], d[mt][nt][1]);
                hbu[(16 * mt + g + 8) * HSTRW + 4 * nt + tg] = packh2(d[mt][nt][2], d[mt][nt][3]);
            }
        }
    }
}

// smem layout (float units):
// BF0 [512] @0 | BF1 [2048] @512 | BF2 [2048] @2560
// params @4608: sb0,sb1,sb2,sg0,sbe0,sg1,sbe1,sg2,sbe2,sw3 (64 each) -> 5248
// hb @5248: 8 warps x 32 rows x 72 halfs (=1152 floats/warp)
#define SMEM_FLOATS (5248 + 8 * 1152)

__global__ __launch_bounds__(256, 2) void edge_mlp_tc(
    const float* __restrict__ x, const int* __restrict__ ei,
    const float* __restrict__ W0, const float* __restrict__ b0,
    const float* __restrict__ g0, const float* __restrict__ be0,
    const float* __restrict__ W1, const float* __restrict__ b1,
    const float* __restrict__ g1, const float* __restrict__ be1,
    const float* __restrict__ W2, const float* __restrict__ b2,
    const float* __restrict__ g2, const float* __restrict__ be2,
    const float* __restrict__ W3, const float* __restrict__ b3,
    float* __restrict__ out, int n_edges)
{
    extern __shared__ float sm[];
    uint2* BF0 = (uint2*)(sm);
    uint2* BF1 = (uint2*)(sm + 512);
    uint2* BF2 = (uint2*)(sm + 2560);
    float* sb0 = sm + 4608; float* sb1 = sm + 4672; float* sb2 = sm + 4736;
    float* sg0 = sm + 4800; float* sbe0 = sm + 4864;
    float* sg1 = sm + 4928; float* sbe1 = sm + 4992;
    float* sg2 = sm + 5056; float* sbe2 = sm + 5120;
    float* sw3 = sm + 5184;

    const int tid = threadIdx.x;

    // Stage B fragments (fp16): b0={W[16kk+2tg][n],W[+1][n]}, b1={W[16kk+2tg+8][n],W[+9][n]}, n=8nt+g
    for (int i = tid; i < 256; i += 256) {   // BF0: kk=0 only (K=16)
        int nt = i >> 5, ln = i & 31, gg = ln >> 2, tt = ln & 3;
        int n = 8 * nt + gg, k0 = 2 * tt;
        BF0[i] = make_uint2(packh2(W0[k0 * 64 + n],       W0[(k0 + 1) * 64 + n]),
                            packh2(W0[(k0 + 8) * 64 + n], W0[(k0 + 9) * 64 + n]));
    }
    for (int i = tid; i < 1024; i += 256) {  // BF1/BF2: kk=0..3
        int kk = i >> 8, nt = (i >> 5) & 7, ln = i & 31, gg = ln >> 2, tt = ln & 3;
        int n = 8 * nt + gg, k0 = 16 * kk + 2 * tt;
        BF1[i] = make_uint2(packh2(W1[k0 * 64 + n],       W1[(k0 + 1) * 64 + n]),
                            packh2(W1[(k0 + 8) * 64 + n], W1[(k0 + 9) * 64 + n]));
        BF2[i] = make_uint2(packh2(W2[k0 * 64 + n],       W2[(k0 + 1) * 64 + n]),
                            packh2(W2[(k0 + 8) * 64 + n], W2[(k0 + 9) * 64 + n]));
    }
    if (tid < 64) {
        sb0[tid] = b0[tid]; sb1[tid] = b1[tid]; sb2[tid] = b2[tid];
        sg0[tid] = g0[tid]; sbe0[tid] = be0[tid];
        sg1[tid] = g1[tid]; sbe1[tid] = be1[tid];
        sg2[tid] = g2[tid]; sbe2[tid] = be2[tid];
        sw3[tid] = W3[tid];
    }
    __syncthreads();
    const float b3v = b3[0];

    const int lane = tid & 31, wid = tid >> 5;
    const int g = lane >> 2, tg = lane & 3;
    unsigned* hbu = (unsigned*)(sm + 5248) + wid * (32 * HSTRW);
    const float4* x4 = (const float4*)x;

    const int tile_stride = gridDim.x * 8 * 32;
    for (int base = (blockIdx.x * 8 + wid) * 32; base < n_edges; base += tile_stride) {
        // gather 32 edges -> hb row `lane`, 16 halfs
        int e = base + lane; if (e >= n_edges) e = n_edges - 1;
        int si = ei[e], di = ei[n_edges + e];
        float4 A0 = x4[2 * si], A1 = x4[2 * si + 1];
        float4 C0 = x4[2 * di], C1 = x4[2 * di + 1];
        {
            unsigned* hr = &hbu[lane * HSTRW];
            uint4 lo = make_uint4(packh2(A0.x, A0.y), packh2(A0.z, A0.w),
                                  packh2(A1.x, A1.y), packh2(A1.z, A1.w));
            uint4 hi = make_uint4(packh2(C0.x, C0.y), packh2(C0.z, C0.w),
                                  packh2(C1.x, C1.y), packh2(C1.z, C1.w));
            *(uint4*)&hr[0] = lo;
            *(uint4*)&hr[4] = hi;
        }
        __syncwarp();

        float d[2][8][4];

        // layer 0: K=16 (1 MMA step)
        init_bias(d, sb0, tg);
        mma_layer<1>(d, BF0, hbu, g, tg, lane);
        __syncwarp();
        ln_tanh_frag<true>(d, sg0, sbe0, hbu, g, tg);
        __syncwarp();

        // layer 1: K=64 (4 MMA steps)
        init_bias(d, sb1, tg);
        mma_layer<4>(d, BF1, hbu, g, tg, lane);
        __syncwarp();
        ln_tanh_frag<true>(d, sg1, sbe1, hbu, g, tg);
        __syncwarp();

        // layer 2: K=64 (output stays in registers)
        init_bias(d, sb2, tg);
        mma_layer<4>(d, BF2, hbu, g, tg, lane);
        __syncwarp();   // hb reads done -> safe to overwrite next iteration
        ln_tanh_frag<false>(d, sg2, sbe2, hbu, g, tg);

        // layer 3: 64 -> 1, butterfly reduce over the 4-lane group
#pragma unroll
        for (int mt = 0; mt < 2; mt++) {
            float p1 = 0.f, p2 = 0.f;
#pragma unroll
            for (int nt = 0; nt < 8; nt++) {
                float2 w = *(const float2*)&sw3[8 * nt + 2 * tg];
                p1 = fmaf(d[mt][nt][0], w.x, p1); p1 = fmaf(d[mt][nt][1], w.y, p1);
                p2 = fmaf(d[mt][nt][2], w.x, p2); p2 = fmaf(d[mt][nt][3], w.y, p2);
            }
            p1 += __shfl_xor_sync(0xffffffffu, p1, 1); p1 += __shfl_xor_sync(0xffffffffu, p1, 2);
            p2 += __shfl_xor_sync(0xffffffffu, p2, 1); p2 += __shfl_xor_sync(0xffffffffu, p2, 2);
            if (tg == 0) {
                int e1 = base + 16 * mt + g, e2 = e1 + 8;
                if (e1 < n_edges) out[e1] = p1 + b3v;
                if (e2 < n_edges) out[e2] = p2 + b3v;
            }
        }
        __syncwarp();
    }
}

extern "C" void kernel_launch(void* const* d_in, const int* in_sizes, int n_in,
                              void* d_out, int out_size) {
    const float* x   = (const float*)d_in[0];
    const int*   ei  = (const int*)d_in[1];
    const float* W0 = (const float*)d_in[2];
    const float* b0 = (const float*)d_in[3];
    const float* g0 = (const float*)d_in[4];
    const float* be0 = (const float*)d_in[5];
    const float* W1 = (const float*)d_in[6];
    const float* b1 = (const float*)d_in[7];
    const float* g1 = (const float*)d_in[8];
    const float* be1 = (const float*)d_in[9];
    const float* W2 = (const float*)d_in[10];
    const float* b2 = (const float*)d_in[11];
    const float* g2 = (const float*)d_in[12];
    const float* be2 = (const float*)d_in[13];
    const float* W3 = (const float*)d_in[14];
    const float* b3 = (const float*)d_in[15];
    float* out = (float*)d_out;

    const int n_edges = in_sizes[1] / 2;
    const size_t smem_bytes = SMEM_FLOATS * sizeof(float);  // ~57 KB

    static bool attr_set = false;
    if (!attr_set) {
        cudaFuncSetAttribute(edge_mlp_tc, cudaFuncAttributeMaxDynamicSharedMemorySize,
                             (int)smem_bytes);
        attr_set = true;
    }

    const int threads = 256;
    const int blocks = 296;  // 2 resident blocks/SM, grid-stride
    edge_mlp_tc<<<blocks, threads, smem_bytes>>>(x, ei,
                                                 W0, b0, g0, be0,
                                                 W1, b1, g1, be1,
                                                 W2, b2, g2, be2,
                                                 W3, b3, out, n_edges);
}